// round 3
// baseline (speedup 1.0000x reference)
#include <cuda_runtime.h>

#define TT 64
#define CC 128
#define HD 32

#define XSS 129   // xs stride (odd -> scalar column reads conflict-free)
#define WS  96    // W smem stride (uniform reads, any stride)
#define QS  36    // q stride (mult of 4 -> float4 aligned; 8-row conflict-free)
#define KTS 68    // kT stride (mult of 4)
#define VS  36    // v stride
#define SCS 65    // scores stride (overlays xs)
#define NTHREADS 256

#define OFF_XS 0
#define OFF_W  (TT * XSS)              // 8256
#define OFF_Q  (OFF_W + CC * WS)       // 20544
#define OFF_KT (OFF_Q + TT * QS)       // 22848
#define OFF_V  (OFF_KT + HD * KTS)     // 25024
#define SMEM_FLOATS (OFF_V + TT * VS)  // 27328 floats = 109312 B

typedef unsigned long long u64;

__device__ __forceinline__ u64 splat2(float x) {
    u64 r;
    asm("mov.b64 %0, {%1, %1};" : "=l"(r) : "f"(x));
    return r;
}
__device__ __forceinline__ void ffma2(u64& d, u64 a, u64 b) {
    asm("fma.rn.f32x2 %0, %1, %2, %0;" : "+l"(d) : "l"(a), "l"(b));
}
__device__ __forceinline__ float2 unpack2(u64 a) {
    float lo, hi;
    asm("mov.b64 {%0, %1}, %2;" : "=f"(lo), "=f"(hi) : "l"(a));
    return make_float2(lo, hi);
}

__global__ __launch_bounds__(NTHREADS, 2)
void head_attn_kernel(const float* __restrict__ x,
                      const float* __restrict__ Wq,
                      const float* __restrict__ Wk,
                      const float* __restrict__ Wv,
                      float* __restrict__ out) {
    extern __shared__ float smem[];
    float* xs  = smem + OFF_XS;   // [64][129]; later scores [64][65]
    float* Wsm = smem + OFF_W;    // [128][96]  (cols: q 0-31 | k 32-63 | v 64-95)
    float* qsm = smem + OFF_Q;    // [64][36]
    float* kT  = smem + OFF_KT;   // [32][68]  kT[dim][seqrow]
    float* vsm = smem + OFF_V;    // [64][36]

    const int tid  = threadIdx.x;
    const int warp = tid >> 5;
    const int lane = tid & 31;
    const int b    = blockIdx.x;
    const float* xb = x + (size_t)b * (TT * CC);

    // ---------------- Phase 0: stage x (scalar STS) and W (float4) ----------------
    #pragma unroll
    for (int ii = 0; ii < (TT * CC) / 4 / NTHREADS; ii++) {   // 8 iters
        int i = tid + ii * NTHREADS;
        float4 v4 = reinterpret_cast<const float4*>(xb)[i];
        int idx = i * 4;
        int r = idx >> 7;
        int c = idx & 127;
        float* dst = xs + r * XSS + c;
        dst[0] = v4.x; dst[1] = v4.y; dst[2] = v4.z; dst[3] = v4.w;
    }
    #pragma unroll
    for (int ii = 0; ii < (CC * HD) / 4 / NTHREADS; ii++) {   // 4 iters
        int i = tid + ii * NTHREADS;
        int idx = i * 4;
        int d = idx >> 5;
        int c = idx & 31;
        float4 vq = reinterpret_cast<const float4*>(Wq)[i];
        float4 vk = reinterpret_cast<const float4*>(Wk)[i];
        float4 vv = reinterpret_cast<const float4*>(Wv)[i];
        *reinterpret_cast<float4*>(Wsm + d * WS + c)      = vq;
        *reinterpret_cast<float4*>(Wsm + d * WS + 32 + c) = vk;
        *reinterpret_cast<float4*>(Wsm + d * WS + 64 + c) = vv;
    }
    __syncthreads();

    // ---------------- Phase 1: fused QKV projection ----------------
    // Warp tile: 12 cols x 64 rows. Lane: rows (lane, lane+32) x 12 cols.
    // Per d: 2 scalar x loads (lane-linear, 1 wf each) + 3 uniform W LDS.128.
    {
        const int c0 = warp * 12;
        u64 acc[2][6];
        #pragma unroll
        for (int i = 0; i < 2; i++)
            #pragma unroll
            for (int p = 0; p < 6; p++) acc[i][p] = 0ull;

        const float* xr0 = xs + lane * XSS;
        const float* xr1 = xs + (lane + 32) * XSS;
        const float* wr  = Wsm + c0;

        #pragma unroll 2
        for (int d = 0; d < CC; d++) {
            float x0 = xr0[d];
            float x1 = xr1[d];
            const float* wd = wr + d * WS;
            ulonglong2 w0 = *reinterpret_cast<const ulonglong2*>(wd);
            ulonglong2 w1 = *reinterpret_cast<const ulonglong2*>(wd + 4);
            ulonglong2 w2 = *reinterpret_cast<const ulonglong2*>(wd + 8);
            u64 s0 = splat2(x0);
            u64 s1 = splat2(x1);
            ffma2(acc[0][0], s0, w0.x); ffma2(acc[0][1], s0, w0.y);
            ffma2(acc[0][2], s0, w1.x); ffma2(acc[0][3], s0, w1.y);
            ffma2(acc[0][4], s0, w2.x); ffma2(acc[0][5], s0, w2.y);
            ffma2(acc[1][0], s1, w0.x); ffma2(acc[1][1], s1, w0.y);
            ffma2(acc[1][2], s1, w1.x); ffma2(acc[1][3], s1, w1.y);
            ffma2(acc[1][4], s1, w2.x); ffma2(acc[1][5], s1, w2.y);
        }

        // scatter: cols <32 -> q, 32..63 -> kT (transposed), >=64 -> v
        #pragma unroll
        for (int i = 0; i < 2; i++) {
            int row = lane + 32 * i;
            #pragma unroll
            for (int p = 0; p < 6; p++) {
                float2 v2 = unpack2(acc[i][p]);
                #pragma unroll
                for (int e = 0; e < 2; e++) {
                    int c = c0 + 2 * p + e;
                    float val = (e == 0) ? v2.x : v2.y;
                    if (c < 32)       qsm[row * QS + c] = val;
                    else if (c < 64)  kT[(c - 32) * KTS + row] = val;
                    else              vsm[row * VS + (c - 64)] = val;
                }
            }
        }
    }
    __syncthreads();

    // ---------------- Phase 2: scores = scale * q @ kT ----------------
    // Thread: row r = tid>>2, cols [16g, 16g+16). q row cached in regs.
    {
        const int r  = tid >> 2;
        const int g  = tid & 3;
        const int c0 = g * 16;
        float* sc = xs;   // overlay (x is dead)

        if (c0 <= r) {
            float qreg[32];
            #pragma unroll
            for (int j = 0; j < 8; j++)
                *reinterpret_cast<float4*>(qreg + 4 * j) =
                    *reinterpret_cast<const float4*>(qsm + r * QS + 4 * j);

            u64 acc[8];
            #pragma unroll
            for (int p = 0; p < 8; p++) acc[p] = 0ull;

            #pragma unroll 2
            for (int d = 0; d < HD; d++) {
                const float* kd = kT + d * KTS + c0;
                ulonglong2 k0 = *reinterpret_cast<const ulonglong2*>(kd);
                ulonglong2 k1 = *reinterpret_cast<const ulonglong2*>(kd + 4);
                ulonglong2 k2 = *reinterpret_cast<const ulonglong2*>(kd + 8);
                ulonglong2 k3 = *reinterpret_cast<const ulonglong2*>(kd + 12);
                u64 s = splat2(qreg[d]);
                ffma2(acc[0], s, k0.x); ffma2(acc[1], s, k0.y);
                ffma2(acc[2], s, k1.x); ffma2(acc[3], s, k1.y);
                ffma2(acc[4], s, k2.x); ffma2(acc[5], s, k2.y);
                ffma2(acc[6], s, k3.x); ffma2(acc[7], s, k3.y);
            }

            const float scale = 0.17677669529663687f;  // 1/sqrt(32)
            #pragma unroll
            for (int p = 0; p < 8; p++) {
                float2 v2 = unpack2(acc[p]);
                sc[r * SCS + c0 + 2 * p]     = v2.x * scale;
                sc[r * SCS + c0 + 2 * p + 1] = v2.y * scale;
            }
        }
    }
    __syncthreads();

    // ---------------- Phase 3: causal softmax, one warp per row ----------------
    {
        for (int r = warp; r < TT; r += 8) {
            float* row = xs + r * SCS;
            bool v0 = (lane <= r);
            bool v1 = (lane + 32 <= r);
            float s0 = v0 ? row[lane]      : -1e30f;
            float s1 = v1 ? row[lane + 32] : -1e30f;
            float m = fmaxf(s0, s1);
            #pragma unroll
            for (int off = 16; off > 0; off >>= 1)
                m = fmaxf(m, __shfl_xor_sync(0xffffffffu, m, off));
            float e0 = v0 ? __expf(s0 - m) : 0.0f;
            float e1 = v1 ? __expf(s1 - m) : 0.0f;
            float sum = e0 + e1;
            #pragma unroll
            for (int off = 16; off > 0; off >>= 1)
                sum += __shfl_xor_sync(0xffffffffu, sum, off);
            float inv = 1.0f / sum;
            row[lane]      = e0 * inv;          // zeros where invalid
            row[lane + 32] = e1 * inv;
        }
    }
    __syncthreads();

    // ---------------- Phase 4: out = probs @ v ----------------
    // Thread: row r = tid>>2, cols [8g, 8g+8). Loop to warp-max row
    // (tail probs are exact zeros) to keep loads warp-uniform.
    {
        const int r  = tid >> 2;
        const int g  = tid & 3;
        const int h0 = g * 8;
        const int cend = ((warp << 3) | 7);   // max row in this warp

        u64 acc[4] = {0ull, 0ull, 0ull, 0ull};
        const float* sc = xs;

        for (int c = 0; c <= cend; c++) {
            float p = sc[r * SCS + c];
            const float* vr = vsm + c * VS + h0;
            ulonglong2 v0 = *reinterpret_cast<const ulonglong2*>(vr);
            ulonglong2 v1 = *reinterpret_cast<const ulonglong2*>(vr + 4);
            u64 s = splat2(p);
            ffma2(acc[0], s, v0.x); ffma2(acc[1], s, v0.y);
            ffma2(acc[2], s, v1.x); ffma2(acc[3], s, v1.y);
        }

        float* ob = out + (size_t)b * (TT * HD);
        float2 a0 = unpack2(acc[0]), a1 = unpack2(acc[1]);
        float2 a2 = unpack2(acc[2]), a3 = unpack2(acc[3]);
        *reinterpret_cast<float4*>(ob + r * HD + h0)     =
            make_float4(a0.x, a0.y, a1.x, a1.y);
        *reinterpret_cast<float4*>(ob + r * HD + h0 + 4) =
            make_float4(a2.x, a2.y, a3.x, a3.y);
    }
}

extern "C" void kernel_launch(void* const* d_in, const int* in_sizes, int n_in,
                              void* d_out, int out_size) {
    const float* x  = (const float*)d_in[0];
    const float* Wq = (const float*)d_in[1];
    const float* Wk = (const float*)d_in[2];
    const float* Wv = (const float*)d_in[3];
    float* out = (float*)d_out;

    const int B = in_sizes[0] / (TT * CC);   // 4096
    const size_t smem_bytes = SMEM_FLOATS * sizeof(float);

    static_assert(2 * SMEM_FLOATS * sizeof(float) <= 228 * 1024, "2 CTAs/SM");
    cudaFuncSetAttribute(head_attn_kernel,
                         cudaFuncAttributeMaxDynamicSharedMemorySize,
                         (int)smem_bytes);

    head_attn_kernel<<<B, NTHREADS, smem_bytes>>>(x, Wq, Wk, Wv, out);
}

// round 5
// speedup vs baseline: 1.6675x; 1.6675x over previous
#include <cuda_runtime.h>
#include <cstdint>

#define TT 64
#define CC 128
#define HD 32
#define NTHREADS 256

#define XSS 132    // xs fp32 [64][132]; scores [64][65] overlay this region
#define WSS 100    // W tf32 bits [128][100]
#define QKVS 97    // qkv fp32 [64][97]: q 0-31 | k 32-63 | v 64-95 (R1 layout)
#define SCS 65     // scores stride (overlays xs)

#define OFF_XS  0
#define OFF_W   (TT * XSS)                 // 8448
#define OFF_QKV (OFF_W + CC * WSS)         // 21248
#define SMEM_FLOATS (OFF_QKV + TT * QKVS)  // 27456 floats = 109824 B

__device__ __forceinline__ uint32_t f2tf(float f) {
    uint32_t u;
    asm("cvt.rna.tf32.f32 %0, %1;" : "=r"(u) : "f"(f));
    return u;
}
__device__ __forceinline__ void split_tf(float f, uint32_t& hi, uint32_t& lo) {
    hi = f2tf(f);
    lo = f2tf(f - __uint_as_float(hi));
}
__device__ __forceinline__ void mma_tf32(float c[4],
                                         uint32_t a0, uint32_t a1, uint32_t a2, uint32_t a3,
                                         uint32_t b0, uint32_t b1) {
    asm("mma.sync.aligned.m16n8k8.row.col.f32.tf32.tf32.f32 "
        "{%0,%1,%2,%3},{%4,%5,%6,%7},{%8,%9},{%0,%1,%2,%3};"
        : "+f"(c[0]), "+f"(c[1]), "+f"(c[2]), "+f"(c[3])
        : "r"(a0), "r"(a1), "r"(a2), "r"(a3), "r"(b0), "r"(b1));
}

__global__ __launch_bounds__(NTHREADS, 2)
void head_attn_kernel(const float* __restrict__ x,
                      const float* __restrict__ Wq,
                      const float* __restrict__ Wk,
                      const float* __restrict__ Wv,
                      float* __restrict__ out) {
    extern __shared__ float smem[];
    float*    xs  = smem + OFF_XS;                               // fp32 x; later scores
    uint32_t* Wu  = reinterpret_cast<uint32_t*>(smem + OFF_W);   // tf32 bits [128][100]
    float*    qkv = smem + OFF_QKV;                              // fp32 [64][97]

    const int tid  = threadIdx.x;
    const int warp = tid >> 5;
    const int lane = tid & 31;
    const int gid  = lane >> 2;   // 0..7
    const int tig  = lane & 3;    // 0..3
    const int b    = blockIdx.x;
    const float* xb = x + (size_t)b * (TT * CC);

    // ---------------- Phase 0: stage x (fp32) and W (tf32 bits) ----------------
    #pragma unroll
    for (int ii = 0; ii < (TT * CC) / 4 / NTHREADS; ii++) {   // 8
        int i = tid + ii * NTHREADS;
        float4 v4 = reinterpret_cast<const float4*>(xb)[i];
        int idx = i * 4;
        int r = idx >> 7, c = idx & 127;
        *reinterpret_cast<float4*>(xs + r * XSS + c) = v4;
    }
    #pragma unroll
    for (int ii = 0; ii < (CC * HD) / 4 / NTHREADS; ii++) {   // 4
        int i = tid + ii * NTHREADS;
        int idx = i * 4;
        int d = idx >> 5, c = idx & 31;
        float4 vq = reinterpret_cast<const float4*>(Wq)[i];
        float4 vk = reinterpret_cast<const float4*>(Wk)[i];
        float4 vv = reinterpret_cast<const float4*>(Wv)[i];
        uint4 uq = make_uint4(f2tf(vq.x), f2tf(vq.y), f2tf(vq.z), f2tf(vq.w));
        uint4 uk = make_uint4(f2tf(vk.x), f2tf(vk.y), f2tf(vk.z), f2tf(vk.w));
        uint4 uv = make_uint4(f2tf(vv.x), f2tf(vv.y), f2tf(vv.z), f2tf(vv.w));
        *reinterpret_cast<uint4*>(Wu + d * WSS + c)      = uq;
        *reinterpret_cast<uint4*>(Wu + d * WSS + 32 + c) = uk;
        *reinterpret_cast<uint4*>(Wu + d * WSS + 64 + c) = uv;
    }
    __syncthreads();

    // ---------------- Phase 1: QKV projection via tf32 MMA (hi/lo split A) ----------------
    // M=64 (4 m-tiles of 16), N=96 (12 n-tiles of 8), K=128 (16 steps of 8).
    // warp: m-tile = warp&3, n-tiles = 6*(warp>>2) + 0..5.
    {
        const int m0    = (warp & 3) * 16;
        const int nbase = (warp >> 2) * 48;

        float acc[6][4];
        #pragma unroll
        for (int j = 0; j < 6; j++)
            #pragma unroll
            for (int t = 0; t < 4; t++) acc[j][t] = 0.0f;

        for (int k0 = 0; k0 < CC; k0 += 8) {
            float a0 = xs[(m0 + gid)     * XSS + k0 + tig];
            float a1 = xs[(m0 + gid + 8) * XSS + k0 + tig];
            float a2 = xs[(m0 + gid)     * XSS + k0 + tig + 4];
            float a3 = xs[(m0 + gid + 8) * XSS + k0 + tig + 4];
            uint32_t h0, l0, h1, l1, h2, l2, h3, l3;
            split_tf(a0, h0, l0); split_tf(a1, h1, l1);
            split_tf(a2, h2, l2); split_tf(a3, h3, l3);
            #pragma unroll
            for (int j = 0; j < 6; j++) {
                int n0 = nbase + 8 * j;
                uint32_t b0 = Wu[(k0 + tig)     * WSS + n0 + gid];
                uint32_t b1 = Wu[(k0 + tig + 4) * WSS + n0 + gid];
                mma_tf32(acc[j], h0, h1, h2, h3, b0, b1);
                mma_tf32(acc[j], l0, l1, l2, l3, b0, b1);
            }
        }

        // scatter plain fp32 into R1-layout qkv buffer
        #pragma unroll
        for (int j = 0; j < 6; j++) {
            int n0 = nbase + 8 * j;
            int c  = n0 + 2 * tig;
            #pragma unroll
            for (int half = 0; half < 2; half++) {
                int row = m0 + gid + 8 * half;
                qkv[row * QKVS + c]     = acc[j][2 * half];
                qkv[row * QKVS + c + 1] = acc[j][2 * half + 1];
            }
        }
    }
    __syncthreads();

    // ============ Phases 2-4: VERBATIM R1 (proven correct) ============

    // ---------------- Phase 2: scores = scale * q @ k^T ----------------
    {
        const int ct = tid & 15;
        const int rt = tid >> 4;
        const int c0 = ct * 4;
        const int r0 = rt * 4;
        float* sc = xs;

        if (c0 <= r0 + 3) {
            float acc[4][4];
            #pragma unroll
            for (int i = 0; i < 4; i++)
                #pragma unroll
                for (int j = 0; j < 4; j++) acc[i][j] = 0.0f;

            #pragma unroll 4
            for (int d = 0; d < HD; d++) {
                float qv[4], kv[4];
                #pragma unroll
                for (int i = 0; i < 4; i++) qv[i] = qkv[(r0 + i) * QKVS + d];
                #pragma unroll
                for (int j = 0; j < 4; j++) kv[j] = qkv[(c0 + j) * QKVS + 32 + d];
                #pragma unroll
                for (int i = 0; i < 4; i++)
                    #pragma unroll
                    for (int j = 0; j < 4; j++) acc[i][j] = fmaf(qv[i], kv[j], acc[i][j]);
            }

            const float scale = 0.17677669529663687f;  // 1/sqrt(32)
            #pragma unroll
            for (int i = 0; i < 4; i++)
                #pragma unroll
                for (int j = 0; j < 4; j++)
                    sc[(r0 + i) * SCS + c0 + j] = acc[i][j] * scale;
        }
    }
    __syncthreads();

    // ---------------- Phase 3: causal softmax, one warp per row ----------------
    {
        for (int r = warp; r < TT; r += 8) {
            float* row = xs + r * SCS;
            bool v0 = (lane <= r);
            bool v1 = (lane + 32 <= r);
            float s0 = v0 ? row[lane]      : -1e30f;
            float s1 = v1 ? row[lane + 32] : -1e30f;
            float m = fmaxf(s0, s1);
            #pragma unroll
            for (int off = 16; off > 0; off >>= 1)
                m = fmaxf(m, __shfl_xor_sync(0xffffffffu, m, off));
            float e0 = v0 ? __expf(s0 - m) : 0.0f;
            float e1 = v1 ? __expf(s1 - m) : 0.0f;
            float sum = e0 + e1;
            #pragma unroll
            for (int off = 16; off > 0; off >>= 1)
                sum += __shfl_xor_sync(0xffffffffu, sum, off);
            float inv = 1.0f / sum;
            row[lane]      = e0 * inv;
            row[lane + 32] = e1 * inv;
        }
    }
    __syncthreads();

    // ---------------- Phase 4: out = probs @ v ----------------
    {
        const int ct = tid & 7;
        const int rt = tid >> 3;
        const int h0 = ct * 4;
        const int r0 = rt * 2;

        float acc0[4] = {0.f, 0.f, 0.f, 0.f};
        float acc1[4] = {0.f, 0.f, 0.f, 0.f};
        const int cmax = r0 + 1;

        for (int c = 0; c <= cmax; c++) {
            float p0 = xs[r0 * SCS + c];
            float p1 = xs[(r0 + 1) * SCS + c];
            const float* vr = qkv + c * QKVS + 64 + h0;
            #pragma unroll
            for (int j = 0; j < 4; j++) {
                float vv = vr[j];
                acc0[j] = fmaf(p0, vv, acc0[j]);
                acc1[j] = fmaf(p1, vv, acc1[j]);
            }
        }

        float* ob = out + (size_t)b * (TT * HD);
        *reinterpret_cast<float4*>(ob + r0 * HD + h0) =
            make_float4(acc0[0], acc0[1], acc0[2], acc0[3]);
        *reinterpret_cast<float4*>(ob + (r0 + 1) * HD + h0) =
            make_float4(acc1[0], acc1[1], acc1[2], acc1[3]);
    }
}

extern "C" void kernel_launch(void* const* d_in, const int* in_sizes, int n_in,
                              void* d_out, int out_size) {
    const float* x  = (const float*)d_in[0];
    const float* Wq = (const float*)d_in[1];
    const float* Wk = (const float*)d_in[2];
    const float* Wv = (const float*)d_in[3];
    float* out = (float*)d_out;

    const int B = in_sizes[0] / (TT * CC);   // 4096
    const size_t smem_bytes = SMEM_FLOATS * sizeof(float);

    static_assert(2 * SMEM_FLOATS * sizeof(float) <= 228 * 1024, "2 CTAs/SM");
    cudaFuncSetAttribute(head_attn_kernel,
                         cudaFuncAttributeMaxDynamicSharedMemorySize,
                         (int)smem_bytes);

    head_attn_kernel<<<B, NTHREADS, smem_bytes>>>(x, Wq, Wk, Wv, out);
}

// round 7
// speedup vs baseline: 2.1145x; 1.2680x over previous
#include <cuda_runtime.h>
#include <cstdint>

#define TT 64
#define CC 128
#define HD 32
#define NTHREADS 256

// Bank rules (lane = 4*gid + tig):
//  A-operand loads  arr[(m0+gid)*S + k0+tig]      -> need S ≡ 4 (mod 32)
//  B-operand loads  arr[(k0+tig)*S + n0+gid]      -> need S ≡ 8 (mod 32)
//  B-operand loads  arr[(n0+gid)*S + k0+tig]      -> need S ≡ 4 (mod 32)
#define XSS 132    // xs fp32 [64][132]         (A)        extent 128 ✓
#define SCS 68     // scores fp32 [64][68]      (A, overlay xs)
#define WSS 104    // W tf32 [128][104]         (B, k-major) extent 96 ✓
#define QSS 36     // q fp32 [64][36]           (A)        extent 32 ✓
#define KSS 36     // k tf32 [64][36] row-major (B via n-major) extent 32 ✓
#define VTS 68     // vT tf32 [32][68] [d][seq] (B via n-major) extent 64 ✓

#define OFF_XS 0
#define OFF_W  (TT * XSS)                  // 8448
#define OFF_Q  (OFF_W + CC * WSS)          // 21760
#define OFF_K  (OFF_Q + TT * QSS)          // 24064
#define OFF_VT (OFF_K + TT * KSS)          // 26368
#define SMEM_FLOATS (OFF_VT + HD * VTS)    // 28544 floats = 114176 B

__device__ __forceinline__ uint32_t f2tf(float f) {
    uint32_t u;
    asm("cvt.rna.tf32.f32 %0, %1;" : "=r"(u) : "f"(f));
    return u;
}
__device__ __forceinline__ void split_tf(float f, uint32_t& hi, uint32_t& lo) {
    hi = f2tf(f);
    lo = f2tf(f - __uint_as_float(hi));
}
__device__ __forceinline__ void mma_tf32(float c[4],
                                         uint32_t a0, uint32_t a1, uint32_t a2, uint32_t a3,
                                         uint32_t b0, uint32_t b1) {
    asm("mma.sync.aligned.m16n8k8.row.col.f32.tf32.tf32.f32 "
        "{%0,%1,%2,%3},{%4,%5,%6,%7},{%8,%9},{%0,%1,%2,%3};"
        : "+f"(c[0]), "+f"(c[1]), "+f"(c[2]), "+f"(c[3])
        : "r"(a0), "r"(a1), "r"(a2), "r"(a3), "r"(b0), "r"(b1));
}

__global__ __launch_bounds__(NTHREADS, 2)
void head_attn_kernel(const float* __restrict__ x,
                      const float* __restrict__ Wq,
                      const float* __restrict__ Wk,
                      const float* __restrict__ Wv,
                      float* __restrict__ out) {
    extern __shared__ float smem[];
    float*    xs  = smem + OFF_XS;
    uint32_t* Wu  = reinterpret_cast<uint32_t*>(smem + OFF_W);
    float*    qsm = smem + OFF_Q;
    uint32_t* ku  = reinterpret_cast<uint32_t*>(smem + OFF_K);   // k[seq][d]
    uint32_t* vT  = reinterpret_cast<uint32_t*>(smem + OFF_VT);  // vT[d][seq]
    float*    sc  = xs;   // scores/probs overlay, stride SCS

    const int tid  = threadIdx.x;
    const int warp = tid >> 5;
    const int lane = tid & 31;
    const int gid  = lane >> 2;   // 0..7
    const int tig  = lane & 3;    // 0..3
    const int b    = blockIdx.x;
    const float* xb = x + (size_t)b * (TT * CC);

    // ---------------- Phase 0: stage x (fp32) and W (tf32) ----------------
    #pragma unroll
    for (int ii = 0; ii < (TT * CC) / 4 / NTHREADS; ii++) {   // 8
        int i = tid + ii * NTHREADS;
        float4 v4 = reinterpret_cast<const float4*>(xb)[i];
        int idx = i * 4;
        int r = idx >> 7, c = idx & 127;
        *reinterpret_cast<float4*>(xs + r * XSS + c) = v4;
    }
    #pragma unroll
    for (int ii = 0; ii < (CC * HD) / 4 / NTHREADS; ii++) {   // 4
        int i = tid + ii * NTHREADS;
        int idx = i * 4;
        int d = idx >> 5, c = idx & 31;
        float4 vq = reinterpret_cast<const float4*>(Wq)[i];
        float4 vk = reinterpret_cast<const float4*>(Wk)[i];
        float4 vv = reinterpret_cast<const float4*>(Wv)[i];
        *reinterpret_cast<uint4*>(Wu + d * WSS + c) =
            make_uint4(f2tf(vq.x), f2tf(vq.y), f2tf(vq.z), f2tf(vq.w));
        *reinterpret_cast<uint4*>(Wu + d * WSS + 32 + c) =
            make_uint4(f2tf(vk.x), f2tf(vk.y), f2tf(vk.z), f2tf(vk.w));
        *reinterpret_cast<uint4*>(Wu + d * WSS + 64 + c) =
            make_uint4(f2tf(vv.x), f2tf(vv.y), f2tf(vv.z), f2tf(vv.w));
    }
    __syncthreads();

    // ---------------- Phase 1: QKV via tf32 MMA (verified R5) ----------------
    // M=64, N=96, K=128. warp: m-tile = warp&3, n-tiles = 6*(warp>>2)+0..5
    {
        const int m0    = (warp & 3) * 16;
        const int nbase = (warp >> 2) * 48;

        float acc[6][4];
        #pragma unroll
        for (int j = 0; j < 6; j++)
            #pragma unroll
            for (int t = 0; t < 4; t++) acc[j][t] = 0.0f;

        for (int k0 = 0; k0 < CC; k0 += 8) {
            float a0 = xs[(m0 + gid)     * XSS + k0 + tig];
            float a1 = xs[(m0 + gid + 8) * XSS + k0 + tig];
            float a2 = xs[(m0 + gid)     * XSS + k0 + tig + 4];
            float a3 = xs[(m0 + gid + 8) * XSS + k0 + tig + 4];
            uint32_t h0, l0, h1, l1, h2, l2, h3, l3;
            split_tf(a0, h0, l0); split_tf(a1, h1, l1);
            split_tf(a2, h2, l2); split_tf(a3, h3, l3);
            #pragma unroll
            for (int j = 0; j < 6; j++) {
                int n0 = nbase + 8 * j;
                uint32_t b0 = Wu[(k0 + tig)     * WSS + n0 + gid];
                uint32_t b1 = Wu[(k0 + tig + 4) * WSS + n0 + gid];
                mma_tf32(acc[j], h0, h1, h2, h3, b0, b1);
                mma_tf32(acc[j], l0, l1, l2, l3, b0, b1);
            }
        }

        // scatter: n<32 -> q fp32 [seq][d]; 32..63 -> k tf32 [seq][d];
        //          >=64 -> vT tf32 [d][seq]
        #pragma unroll
        for (int j = 0; j < 6; j++) {
            int n0 = nbase + 8 * j;
            int c  = n0 + 2 * tig;
            #pragma unroll
            for (int half = 0; half < 2; half++) {
                int row = m0 + gid + 8 * half;
                float v0 = acc[j][2 * half];
                float v1 = acc[j][2 * half + 1];
                if (n0 < 32) {
                    qsm[row * QSS + c]     = v0;
                    qsm[row * QSS + c + 1] = v1;
                } else if (n0 < 64) {
                    ku[row * KSS + (c - 32)] = f2tf(v0);
                    ku[row * KSS + (c - 31)] = f2tf(v1);
                } else {
                    vT[(c - 64) * VTS + row] = f2tf(v0);
                    vT[(c - 63) * VTS + row] = f2tf(v1);
                }
            }
        }
    }
    __syncthreads();

    // ---------------- Phase 2: scores via tf32 MMA ----------------
    // M=64, N=64, K=32. warp: m-tile i=warp&3, n-tiles j=(warp>>2)+2t, j<=2i+1
    {
        const int i  = warp & 3;
        const int m0 = 16 * i;
        const int jb = warp >> 2;
        int jn[4], cnt = 0;
        #pragma unroll
        for (int t = 0; t < 4; t++) {
            int j = jb + 2 * t;
            if (j <= 2 * i + 1) jn[cnt++] = j;
        }

        float acc[4][4];
        #pragma unroll
        for (int t = 0; t < 4; t++)
            #pragma unroll
            for (int e = 0; e < 4; e++) acc[t][e] = 0.0f;

        for (int k0 = 0; k0 < HD; k0 += 8) {
            float a0 = qsm[(m0 + gid)     * QSS + k0 + tig];
            float a1 = qsm[(m0 + gid + 8) * QSS + k0 + tig];
            float a2 = qsm[(m0 + gid)     * QSS + k0 + tig + 4];
            float a3 = qsm[(m0 + gid + 8) * QSS + k0 + tig + 4];
            uint32_t h0, l0, h1, l1, h2, l2, h3, l3;
            split_tf(a0, h0, l0); split_tf(a1, h1, l1);
            split_tf(a2, h2, l2); split_tf(a3, h3, l3);
            for (int t = 0; t < cnt; t++) {
                int n0 = 8 * jn[t];
                // B element (k, n) = k[seq=n][d=k]: row-major k, n-major load
                uint32_t b0 = ku[(n0 + gid) * KSS + k0 + tig];
                uint32_t b1 = ku[(n0 + gid) * KSS + k0 + tig + 4];
                mma_tf32(acc[t], h0, h1, h2, h3, b0, b1);
                mma_tf32(acc[t], l0, l1, l2, l3, b0, b1);
            }
        }

        const float scale = 0.17677669529663687f;   // 1/sqrt(32)
        for (int t = 0; t < cnt; t++) {
            int n0 = 8 * jn[t];
            int c  = n0 + 2 * tig;
            #pragma unroll
            for (int half = 0; half < 2; half++) {
                int row = m0 + gid + 8 * half;
                sc[row * SCS + c]     = acc[t][2 * half]     * scale;
                sc[row * SCS + c + 1] = acc[t][2 * half + 1] * scale;
            }
        }
    }
    __syncthreads();

    // ---------------- Phase 3: causal softmax, one warp per row ----------------
    {
        for (int r = warp; r < TT; r += 8) {
            float* row = sc + r * SCS;
            bool v0 = (lane <= r);
            bool v1 = (lane + 32 <= r);
            float s0 = v0 ? row[lane]      : -1e30f;
            float s1 = v1 ? row[lane + 32] : -1e30f;
            float m = fmaxf(s0, s1);
            #pragma unroll
            for (int off = 16; off > 0; off >>= 1)
                m = fmaxf(m, __shfl_xor_sync(0xffffffffu, m, off));
            float e0 = v0 ? __expf(s0 - m) : 0.0f;
            float e1 = v1 ? __expf(s1 - m) : 0.0f;
            float sum = e0 + e1;
            #pragma unroll
            for (int off = 16; off > 0; off >>= 1)
                sum += __shfl_xor_sync(0xffffffffu, sum, off);
            float inv = 1.0f / sum;
            row[lane]      = e0 * inv;   // exact zeros where masked
            row[lane + 32] = e1 * inv;
        }
    }
    __syncthreads();

    // ---------------- Phase 4: out = P @ V via tf32 MMA ----------------
    // M=64, N=32, K=64 causal-truncated. warp: m-tile i=warp&3, n-tiles jb, jb+2
    {
        const int i  = warp & 3;
        const int m0 = 16 * i;
        const int jb = warp >> 2;

        float acc[2][4];
        #pragma unroll
        for (int t = 0; t < 2; t++)
            #pragma unroll
            for (int e = 0; e < 4; e++) acc[t][e] = 0.0f;

        const int kend = 16 * i + 8;   // probs beyond are exact zeros
        for (int k0 = 0; k0 <= kend; k0 += 8) {
            float a0 = sc[(m0 + gid)     * SCS + k0 + tig];
            float a1 = sc[(m0 + gid + 8) * SCS + k0 + tig];
            float a2 = sc[(m0 + gid)     * SCS + k0 + tig + 4];
            float a3 = sc[(m0 + gid + 8) * SCS + k0 + tig + 4];
            uint32_t h0, l0, h1, l1, h2, l2, h3, l3;
            split_tf(a0, h0, l0); split_tf(a1, h1, l1);
            split_tf(a2, h2, l2); split_tf(a3, h3, l3);
            #pragma unroll
            for (int t = 0; t < 2; t++) {
                int n0 = 8 * (jb + 2 * t);
                // B element (k, n) = vT[d=n][seq=k]: n-major load
                uint32_t b0 = vT[(n0 + gid) * VTS + k0 + tig];
                uint32_t b1 = vT[(n0 + gid) * VTS + k0 + tig + 4];
                mma_tf32(acc[t], h0, h1, h2, h3, b0, b1);
                mma_tf32(acc[t], l0, l1, l2, l3, b0, b1);
            }
        }

        float* ob = out + (size_t)b * (TT * HD);
        #pragma unroll
        for (int t = 0; t < 2; t++) {
            int n0 = 8 * (jb + 2 * t);
            int c  = n0 + 2 * tig;
            #pragma unroll
            for (int half = 0; half < 2; half++) {
                int row = m0 + gid + 8 * half;
                *reinterpret_cast<float2*>(ob + row * HD + c) =
                    make_float2(acc[t][2 * half], acc[t][2 * half + 1]);
            }
        }
    }
}

extern "C" void kernel_launch(void* const* d_in, const int* in_sizes, int n_in,
                              void* d_out, int out_size) {
    const float* x  = (const float*)d_in[0];
    const float* Wq = (const float*)d_in[1];
    const float* Wk = (const float*)d_in[2];
    const float* Wv = (const float*)d_in[3];
    float* out = (float*)d_out;

    const int B = in_sizes[0] / (TT * CC);   // 4096
    const size_t smem_bytes = SMEM_FLOATS * sizeof(float);

    static_assert(2 * (SMEM_FLOATS * sizeof(float) + 1024) <= 228 * 1024,
                  "2 CTAs/SM incl. per-CTA reserve");
    cudaFuncSetAttribute(head_attn_kernel,
                         cudaFuncAttributeMaxDynamicSharedMemorySize,
                         (int)smem_bytes);

    head_attn_kernel<<<B, NTHREADS, smem_bytes>>>(x, Wq, Wk, Wv, out);
}